// round 11
// baseline (speedup 1.0000x reference)
#include <cuda_runtime.h>
#include <cuda_fp16.h>
#include <cstdint>

typedef unsigned long long ull;

#define Bsz 1024
#define Dd  1024
#define Ff  32768
#define L0  32
#define BN  128
#define NT  (Ff/BN)        // 256 candidate tiles (128 cols each) -- K2 granularity
#define NT2 (Ff/256)       // 128 GEMM column tiles (256 cols each)
#define KC  64             // K dims per chunk
#define NCH (Dd/KC)        // 16 chunks
#define TILE_B 16384       // 128 rows x 64 fp16 = 16KB
#define NTSEL 10           // tiles rescored (2 atoms each)
#define HROWS 512          // rows per stream half
#define HMT   (HROWS/128)  // m-tiles per half
#define STAGE_B 49152      // 16KB A + 2x16KB B per stage
#define GEMM_SMEM (2*STAGE_B + 256)

// ---------------- persistent device scratch ----------------
__device__ float g_resid[Bsz*Dd];
__device__ __align__(16) ull g_xs_t[(size_t)Ff*Dd/4];   // 64MB fp16 tiled/swizzled dict
__device__ __align__(16) ull g_a_t[(size_t)Bsz*Dd/4];   // 2MB fp16 tiled residual
__device__ float g_cand_val[Bsz*NT];
__device__ int   g_cand_idx[Bsz*NT];
__device__ float g_cand_val2[Bsz*NT];
__device__ int   g_cand_idx2[Bsz*NT];
__device__ int   g_nsel[Bsz];
__device__ int   g_sel_idx[Bsz*34];
__device__ float g_sel_w[Bsz*34];

// ---------------- helpers ----------------
__device__ __forceinline__ uint32_t smem_u32(const void* p){
    uint32_t a; asm("{ .reg .u64 t; cvta.to.shared.u64 t, %1; cvt.u32.u64 %0, t; }"
                    : "=r"(a) : "l"(p)); return a;
}
__device__ __forceinline__ void cp16(uint32_t dst, const void* src){
    asm volatile("cp.async.cg.shared.global [%0], [%1], 16;" :: "r"(dst), "l"(src) : "memory");
}
__device__ __forceinline__ void cp_commit(){ asm volatile("cp.async.commit_group;" ::: "memory"); }
__device__ __forceinline__ void cp_wait1(){ asm volatile("cp.async.wait_group 1;" ::: "memory"); }
__device__ __forceinline__ void cp_wait0(){ asm volatile("cp.async.wait_group 0;" ::: "memory"); }
__device__ __forceinline__ void ldmx4(uint32_t* r, uint32_t addr){
    asm volatile("ldmatrix.sync.aligned.m8n8.x4.shared.b16 {%0,%1,%2,%3}, [%4];"
        : "=r"(r[0]), "=r"(r[1]), "=r"(r[2]), "=r"(r[3]) : "r"(addr));
}
// fp16 inputs, fp16 accumulators (2 regs)
__device__ __forceinline__ void mma_f16acc(uint32_t* d, const uint32_t* a, uint32_t b0, uint32_t b1){
    asm volatile("mma.sync.aligned.m16n8k16.row.col.f16.f16.f16.f16 "
        "{%0,%1}, {%2,%3,%4,%5}, {%6,%7}, {%0,%1};"
        : "+r"(d[0]), "+r"(d[1])
        : "r"(a[0]), "r"(a[1]), "r"(a[2]), "r"(a[3]), "r"(b0), "r"(b1));
}
__device__ __forceinline__ uint32_t swoff(int row, int colb){
    uint32_t o = (uint32_t)(row*128 + colb);
    return o ^ ((o >> 3) & 0x70);
}
__device__ __forceinline__ ull pack4h(float a, float b, float c, float d){
    const __half2 lo = __floats2half2_rn(a, b);
    const __half2 hi = __floats2half2_rn(c, d);
    const uint32_t ulo = *reinterpret_cast<const uint32_t*>(&lo);
    const uint32_t uhi = *reinterpret_cast<const uint32_t*>(&hi);
    return (ull)ulo | ((ull)uhi << 32);
}
__device__ __forceinline__ void store_resid_f16(int b, int tid, float4 v){
    const int m_tile = b >> 7, row = b & 127;
    const int kc = tid >> 4, cg = tid & 15;
    char* dst = (char*)g_a_t + (size_t)(m_tile*NCH + kc)*TILE_B;
    *(ull*)(dst + swoff(row, cg*8)) = pack4h(v.x, v.y, v.z, v.w);
}
__device__ __forceinline__ float block_sum(float v, float* s){
    const int lane = threadIdx.x & 31, w = threadIdx.x >> 5;
#pragma unroll
    for (int o = 16; o; o >>= 1) v += __shfl_xor_sync(0xffffffffu, v, o);
    __syncthreads();
    if (lane == 0) s[w] = v;
    __syncthreads();
    float r = 0.f;
#pragma unroll
    for (int i = 0; i < 8; i++) r += s[i];
    return r;
}
__device__ __forceinline__ bool better(float a, int ai, float b, int bi){
    return (a > b) || (a == b && ai < bi);
}
__device__ __forceinline__ void top2_push(float &v1, int &i1, float &v2, int &i2, float w, int j){
    if (better(w, j, v1, i1)){ v2 = v1; i2 = i1; v1 = w; i1 = j; }
    else if (better(w, j, v2, i2)){ v2 = w; i2 = j; }
}
// warp-parallel exact fp32 dot: atom (gmem) . residual (smem), 1024 dims
__device__ __forceinline__ float warp_dot(const float* __restrict__ atom,
                                          const float* __restrict__ s_resid, int lane){
    const float4* av = (const float4*)atom;
    const float4* rv = (const float4*)s_resid;
    float s = 0.f;
#pragma unroll
    for (int q = 0; q < 8; q++){
        const float4 a = av[lane + q*32];
        const float4 r = rv[lane + q*32];
        s += a.x*r.x + a.y*r.y + a.z*r.z + a.w*r.w;
    }
#pragma unroll
    for (int o = 16; o; o >>= 1) s += __shfl_xor_sync(0xffffffffu, s, o);
    return s;
}

// ---------------- K-1: dictionary -> tiled/swizzled fp16 ----------------
__global__ void conv_xs(const float* __restrict__ xs){
    const int tile = blockIdx.x;               // n_tile*NCH + kc
    const int n_tile = tile >> 4, kc = tile & 15;
    char* dst = (char*)g_xs_t + (size_t)tile*TILE_B;
    for (int g = threadIdx.x; g < 2048; g += 256){
        const int row = g >> 4, cg = g & 15;
        const float4 v = *(const float4*)(xs + (size_t)(n_tile*128 + row)*Dd + kc*KC + cg*4);
        *(ull*)(dst + swoff(row, cg*8)) = pack4h(v.x, v.y, v.z, v.w);
    }
}

// ---------------- K0: residual = x (half-batch) ----------------
__global__ void itda_init(const float* __restrict__ x, int row0){
    const int b = row0 + blockIdx.x;
    const float4 v = ((const float4*)(x + (size_t)b*Dd))[threadIdx.x];
    ((float4*)(g_resid + (size_t)b*Dd))[threadIdx.x] = v;
    store_resid_f16(b, threadIdx.x, v);
    if (threadIdx.x == 0) g_nsel[b] = 0;
}

// ---------------- K1: fp16 HMMA GEMM, CTA 128x256, warp tile 64x64 -------------
// 8 warps: warp_m = wid>>2 (2 x 64 rows), warp_n = wid&3 (4 x 64 cols)
__global__ void __launch_bounds__(256, 2) itda_gemm_mma(int mt0){
    extern __shared__ __align__(16) char smem_raw[];
    uint32_t sb = (smem_u32(smem_raw) + 127u) & ~127u;
    const int tid = threadIdx.x, wid = tid >> 5, lane = tid & 31;
    const int mt = mt0 + blockIdx.x, nt2 = blockIdx.y;
    const int warp_m = wid >> 2, warp_n = wid & 3;

    const char* gA  = (const char*)g_a_t  + (size_t)mt*NCH*TILE_B;
    const char* gB0 = (const char*)g_xs_t + (size_t)(nt2*2    )*NCH*TILE_B;
    const char* gB1 = (const char*)g_xs_t + (size_t)(nt2*2 + 1)*NCH*TILE_B;

    uint32_t acc[4][8][2];                     // f16x2 accumulators (64 regs)
#pragma unroll
    for (int i = 0; i < 4; i++)
#pragma unroll
        for (int j = 0; j < 8; j++){ acc[i][j][0] = 0u; acc[i][j][1] = 0u; }

    const int lrow = ((lane >> 3) & 1)*8 + (lane & 7);
    const int lkb  = (lane >> 4)*16;
    const int rA0  = warp_m*64 + lrow;
    const int bimg = (warp_n >> 1)*16384;              // which 128-col image
    const int rB0  = (warp_n & 1)*64 + lrow;           // row within image

    auto issue = [&](int c, int s){
        const uint32_t dA = sb + s*STAGE_B + tid*16;
        const uint32_t dB = sb + s*STAGE_B + 16384 + tid*16;
        const char* srcA  = gA  + (size_t)c*TILE_B + tid*16;
        const char* srcB0 = gB0 + (size_t)c*TILE_B + tid*16;
        const char* srcB1 = gB1 + (size_t)c*TILE_B + tid*16;
#pragma unroll
        for (int i = 0; i < 4; i++){
            cp16(dA + i*4096,          srcA  + i*4096);
            cp16(dB + i*4096,          srcB0 + i*4096);
            cp16(dB + 16384 + i*4096,  srcB1 + i*4096);
        }
        cp_commit();
    };

    issue(0, 0);
    for (int c = 0; c < NCH; c++){
        const int s = c & 1;
        if (c + 1 < NCH){ issue(c + 1, s ^ 1); cp_wait1(); }
        else            { cp_wait0(); }
        __syncthreads();
        const uint32_t sA = sb + s*STAGE_B;
        const uint32_t sB = sA + 16384 + bimg;
#pragma unroll
        for (int ks = 0; ks < 4; ks++){
            const int kb = ks*32 + lkb;
            uint32_t a[4][4];
#pragma unroll
            for (int mb = 0; mb < 4; mb++)
                ldmx4(a[mb], sA + swoff(rA0 + mb*16, kb));
            uint32_t b[4][4];
#pragma unroll
            for (int nb = 0; nb < 4; nb++)
                ldmx4(b[nb], sB + swoff(rB0 + nb*16, kb));
#pragma unroll
            for (int mb = 0; mb < 4; mb++)
#pragma unroll
                for (int n8 = 0; n8 < 8; n8++){
                    const int nb = n8 >> 1, t = n8 & 1;
                    mma_f16acc(acc[mb][n8], a[mb], b[nb][t], b[nb][2+t]);
                }
        }
        __syncthreads();   // stage s fully consumed before issue(c+2) overwrites it
    }

    // epilogue: per-row top-2 per 64-col quadrant -> merge to per-128-col-half
    float* sval1 = (float*)smem_raw;               // [128][4]
    int*   sidx1 = (int*)(smem_raw + 2048);
    float* sval2 = (float*)(smem_raw + 4096);
    int*   sidx2 = (int*)(smem_raw + 6144);
#pragma unroll
    for (int mb = 0; mb < 4; mb++)
#pragma unroll
        for (int h = 0; h < 2; h++){
            float v1 = -1e30f, v2 = -1e30f; int i1 = 0x7fffffff, i2 = 0x7fffffff;
#pragma unroll
            for (int n8 = 0; n8 < 8; n8++){
                const int c0 = warp_n*64 + n8*8 + (lane & 3)*2;   // col within 256
                const __half2 hh = *reinterpret_cast<const __half2*>(&acc[mb][n8][h]);
                const float2 f2 = __half22float2(hh);
                top2_push(v1, i1, v2, i2, f2.x, c0);
                top2_push(v1, i1, v2, i2, f2.y, c0+1);
            }
#pragma unroll
            for (int o = 1; o <= 2; o <<= 1){
                const float w1 = __shfl_xor_sync(0xffffffffu, v1, o);
                const int   j1 = __shfl_xor_sync(0xffffffffu, i1, o);
                const float w2 = __shfl_xor_sync(0xffffffffu, v2, o);
                const int   j2 = __shfl_xor_sync(0xffffffffu, i2, o);
                top2_push(v1, i1, v2, i2, w1, j1);
                top2_push(v1, i1, v2, i2, w2, j2);
            }
            if ((lane & 3) == 0){
                const int row = warp_m*64 + mb*16 + h*8 + (lane >> 2);
                sval1[row*4 + warp_n] = v1; sidx1[row*4 + warp_n] = i1;
                sval2[row*4 + warp_n] = v2; sidx2[row*4 + warp_n] = i2;
            }
        }
    __syncthreads();
    if (tid < 128){
        const int grow = mt*128 + tid;
#pragma unroll
        for (int half = 0; half < 2; half++){
            const int q0 = half*2, q1 = half*2 + 1;
            float v1 = sval1[tid*4 + q0]; int i1 = sidx1[tid*4 + q0];
            float v2 = sval2[tid*4 + q0]; int i2 = sidx2[tid*4 + q0];
            top2_push(v1, i1, v2, i2, sval1[tid*4 + q1], sidx1[tid*4 + q1]);
            top2_push(v1, i1, v2, i2, sval2[tid*4 + q1], sidx2[tid*4 + q1]);
            const int tile = nt2*2 + half;
            g_cand_val [grow*NT + tile] = v1;
            g_cand_idx [grow*NT + tile] = nt2*256 + i1;
            g_cand_val2[grow*NT + tile] = v2;
            g_cand_idx2[grow*NT + tile] = nt2*256 + i2;
        }
    }
}

// ---------------- K2: warp-parallel rescore/grads + incremental residual -------
__global__ void itda_update(const float* __restrict__ xsm, int row0){
    const int b = row0 + blockIdx.x, tid = threadIdx.x;
    const int wid = tid >> 5, lane = tid & 31;
    __shared__ __align__(16) float s_resid[Dd];
    __shared__ float sred[8];
    __shared__ float s_tv[8];
    __shared__ int   s_ti[8];
    __shared__ int   s_wt[NTSEL];
    __shared__ int   s_win;
    __shared__ int   s_cand[2*NTSEL];
    __shared__ float s_dot[2*NTSEL];
    __shared__ int   s_list[34];
    __shared__ float s_w[34];
    __shared__ float s_grad[34];
    __shared__ int   s_n, s_newpos, s_bidx;
    __shared__ float s_bval;
    __shared__ int   s_nclip;
    __shared__ int   s_clip[34];
    __shared__ float s_cw[34];

    const float4 r4 = ((const float4*)(g_resid + (size_t)b*Dd))[tid];
    ((float4*)s_resid)[tid] = r4;
    if (tid == 0) s_nclip = 0;

    // --- select top-NTSEL tiles by screen tile max ---
    float cv = g_cand_val[b*NT + tid];
    for (int r = 0; r < NTSEL; r++){
        float v = cv; int t = tid;
#pragma unroll
        for (int o = 16; o; o >>= 1){
            const float ov = __shfl_xor_sync(0xffffffffu, v, o);
            const int   ot = __shfl_xor_sync(0xffffffffu, t, o);
            if (better(ov, ot, v, t)){ v = ov; t = ot; }
        }
        if (lane == 0){ s_tv[wid] = v; s_ti[wid] = t; }
        __syncthreads();
        if (tid == 0){
            float bv = s_tv[0]; int bt = s_ti[0];
#pragma unroll
            for (int i = 1; i < 8; i++)
                if (better(s_tv[i], s_ti[i], bv, bt)){ bv = s_tv[i]; bt = s_ti[i]; }
            s_wt[r] = bt; s_win = bt;
        }
        __syncthreads();
        if (tid == s_win) cv = -1e30f;
    }
    if (tid < NTSEL){
        const int w = s_wt[tid];
        s_cand[2*tid+0] = g_cand_idx [b*NT + w];
        s_cand[2*tid+1] = g_cand_idx2[b*NT + w];
    }
    __syncthreads();

    // --- exact fp32 rescore, warp-per-candidate ---
#pragma unroll
    for (int r = 0; r < (2*NTSEL + 7)/8; r++){
        const int k = wid + r*8;
        if (k < 2*NTSEL){
            const float d = warp_dot(xsm + (size_t)s_cand[k]*Dd, s_resid, lane);
            if (lane == 0) s_dot[k] = d;
        }
    }
    __syncthreads();
    if (wid == 0){
        float v = (lane < 2*NTSEL) ? s_dot[lane] : -1e30f;
        int   i = (lane < 2*NTSEL) ? s_cand[lane] : 0x7fffffff;
#pragma unroll
        for (int o = 16; o; o >>= 1){
            const float ov = __shfl_xor_sync(0xffffffffu, v, o);
            const int   oi = __shfl_xor_sync(0xffffffffu, i, o);
            if (better(ov, oi, v, i)){ v = ov; i = oi; }
        }
        if (lane == 0){ s_bidx = i; s_bval = v; }
    }
    __syncthreads();
    const int bidx = s_bidx;

    // --- active list: S = {w>0} U {argmax} ---
    const int n0 = g_nsel[b];
    if (tid < n0){ s_list[tid] = g_sel_idx[b*34 + tid]; s_w[tid] = g_sel_w[b*34 + tid]; }
    __syncthreads();
    if (tid == 0){
        int pos = -1, n = n0;
        for (int j = 0; j < n; j++) if (s_list[j] == bidx){ pos = j; break; }
        if (pos < 0){ pos = n; s_list[n] = bidx; s_w[n] = 0.f; n++; }
        s_n = n; s_newpos = pos;
    }
    __syncthreads();
    const int n = s_n, newpos = s_newpos;

    // --- grads, warp-per-atom ---
    for (int r = 0; r < (n + 7) >> 3; r++){
        const int j = wid + r*8;
        if (j < n){
            if (j == newpos){
                if (lane == 0) s_grad[j] = s_bval;
            } else if (s_w[j] > 0.f){
                const float g = warp_dot(xsm + (size_t)s_list[j]*Dd, s_resid, lane);
                if (lane == 0) s_grad[j] = g;
            } else if (lane == 0) s_grad[j] = 0.f;
        }
    }
    __syncthreads();

    // --- c = grad @ xs (per-thread 4-dim slice) ---
    float4 c4 = make_float4(0.f,0.f,0.f,0.f);
    for (int j = 0; j < n; j++){
        const float g = s_grad[j];
        if (g != 0.f){
            const float4 v = ((const float4*)(xsm + (size_t)s_list[j]*Dd))[tid];
            c4.x += g*v.x; c4.y += g*v.y; c4.z += g*v.z; c4.w += g*v.w;
        }
    }
    const float csq  = block_sum(c4.x*c4.x + c4.y*c4.y + c4.z*c4.z + c4.w*c4.w, sred);
    const float cr   = block_sum(c4.x*r4.x + c4.y*r4.y + c4.z*r4.z + c4.w*r4.w, sred);
    const float step = cr / fmaxf(csq, 1e-3f);

    // --- weight update + clip detection ---
    if (tid < n){
        const float g  = s_grad[tid];
        const float wn = s_w[tid] + step * g;
        s_w[tid] = fmaxf(wn, 0.f);
        if (g != 0.f && wn < 0.f){
            const int p = atomicAdd(&s_nclip, 1);
            s_clip[p] = tid; s_cw[p] = wn;
        }
    }
    __syncthreads();

    // --- incremental residual: r' = r - step*c + sum_clipped (w+s*g)*v ---
    float4 xv;
    xv.x = r4.x - step*c4.x; xv.y = r4.y - step*c4.y;
    xv.z = r4.z - step*c4.z; xv.w = r4.w - step*c4.w;
    const int nclip = s_nclip;
    for (int q = 0; q < nclip; q++){
        const float wneg = s_cw[q];
        const float4 v = ((const float4*)(xsm + (size_t)s_list[s_clip[q]]*Dd))[tid];
        xv.x += wneg*v.x; xv.y += wneg*v.y; xv.z += wneg*v.z; xv.w += wneg*v.w;
    }
    ((float4*)(g_resid + (size_t)b*Dd))[tid] = xv;
    store_resid_f16(b, tid, xv);

    if (tid == 0) g_nsel[b] = n;
    if (tid < n){ g_sel_idx[b*34 + tid] = s_list[tid]; g_sel_w[b*34 + tid] = s_w[tid]; }
}

// ---------------- K3: top_k ordering, padding, decode, losses (half-batch) -----
__global__ void itda_final(const float* __restrict__ xsm, const float* __restrict__ ysm,
                           const float* __restrict__ y,
                           float* __restrict__ wout, float* __restrict__ iout,
                           float* __restrict__ xr, float* __restrict__ yr,
                           float* __restrict__ ls, int row0){
    const int b = row0 + blockIdx.x, tid = threadIdx.x;
    __shared__ int   pi[33];
    __shared__ float pw[33];
    __shared__ int   oidx[32];
    __shared__ float ow[32];
    __shared__ int   s_np;
    __shared__ float sred[8];

    if (tid == 0){
        const int nl = g_nsel[b];
        int np = 0;
        for (int j = 0; j < nl; j++){
            const float w = g_sel_w[b*34 + j];
            if (w > 0.f){ pi[np] = g_sel_idx[b*34 + j]; pw[np] = w; np++; }
        }
        for (int a = 0; a < np; a++){
            int bst = a;
            for (int c = a+1; c < np; c++)
                if (pw[c] > pw[bst] || (pw[c] == pw[bst] && pi[c] < pi[bst])) bst = c;
            const float tw = pw[a]; pw[a] = pw[bst]; pw[bst] = tw;
            const int   ti = pi[a]; pi[a] = pi[bst]; pi[bst] = ti;
        }
        int f = 0;
        for (int k = 0; k < L0; k++){
            if (k < np){ ow[k] = pw[k]; oidx[k] = pi[k]; }
            else {
                for (;;){
                    bool used = false;
                    for (int q = 0; q < np; q++) if (pi[q] == f){ used = true; break; }
                    if (!used) break;
                    f++;
                }
                oidx[k] = f; ow[k] = 0.f; f++;
            }
        }
        s_np = np;
    }
    __syncthreads();

    if (tid < L0){
        wout[b*L0 + tid] = ow[tid];
        iout[b*L0 + tid] = (float)oidx[tid];
    }
    const int np = s_np;

    float4 ax = make_float4(0.f,0.f,0.f,0.f);
    float4 ay = make_float4(0.f,0.f,0.f,0.f);
    for (int k = 0; k < np; k++){
        const float w = ow[k];
        const size_t off = (size_t)oidx[k]*Dd;
        const float4 vx = ((const float4*)(xsm + off))[tid];
        const float4 vy = ((const float4*)(ysm + off))[tid];
        ax.x += w*vx.x; ax.y += w*vx.y; ax.z += w*vx.z; ax.w += w*vx.w;
        ay.x += w*vy.x; ay.y += w*vy.y; ay.z += w*vy.z; ay.w += w*vy.w;
    }
    ((float4*)(xr + (size_t)b*Dd))[tid] = ax;
    ((float4*)(yr + (size_t)b*Dd))[tid] = ay;

    const float4 yv = ((const float4*)(y + (size_t)b*Dd))[tid];
    const float d0 = ay.x - yv.x, d1 = ay.y - yv.y, d2 = ay.z - yv.z, d3 = ay.w - yv.w;
    const float L = block_sum(d0*d0 + d1*d1 + d2*d2 + d3*d3, sred);
    if (tid == 0) ls[b] = L;
}

// ---------------- entry: two forked capture streams, row-disjoint halves -------
extern "C" void kernel_launch(void* const* d_in, const int* in_sizes, int n_in,
                              void* d_out, int out_size){
    const float* x  = (const float*)d_in[0];
    const float* y  = (const float*)d_in[1];
    const float* xs = (const float*)d_in[2];
    const float* ys = (const float*)d_in[3];

    float* out  = (float*)d_out;
    float* wout = out;                    // [1024, 32]
    float* iout = out + Bsz*L0;           // [1024, 32] indices as float
    float* xr   = iout + Bsz*L0;          // [1024, 1024]
    float* yr   = xr + (size_t)Bsz*Dd;    // [1024, 1024]
    float* ls   = yr + (size_t)Bsz*Dd;    // [1024]

    static cudaStream_t s1 = nullptr, s2 = nullptr;
    static cudaEvent_t ev0 = nullptr, evc = nullptr, ev1 = nullptr, ev2 = nullptr;
    if (!s1){
        cudaStreamCreateWithFlags(&s1, cudaStreamNonBlocking);
        cudaStreamCreateWithFlags(&s2, cudaStreamNonBlocking);
        cudaEventCreateWithFlags(&ev0, cudaEventDisableTiming);
        cudaEventCreateWithFlags(&evc, cudaEventDisableTiming);
        cudaEventCreateWithFlags(&ev1, cudaEventDisableTiming);
        cudaEventCreateWithFlags(&ev2, cudaEventDisableTiming);
        cudaFuncSetAttribute(itda_gemm_mma, cudaFuncAttributeMaxDynamicSharedMemorySize, GEMM_SMEM);
    }

    // fork both worker streams off the launch stream
    cudaEventRecord(ev0, 0);
    cudaStreamWaitEvent(s1, ev0, 0);
    cudaStreamWaitEvent(s2, ev0, 0);

    // dict conversion on s1; s2 waits for it before its first GEMM
    conv_xs<<<NT*NCH, 256, 0, s1>>>(xs);
    cudaEventRecord(evc, s1);
    cudaStreamWaitEvent(s2, evc, 0);

    itda_init<<<HROWS, 256, 0, s1>>>(x, 0);
    itda_init<<<HROWS, 256, 0, s2>>>(x, HROWS);

    for (int it = 0; it < L0; it++){
        itda_gemm_mma<<<dim3(HMT, NT2), 256, GEMM_SMEM, s1>>>(0);
        itda_update  <<<HROWS, 256, 0, s1>>>(xs, 0);
        itda_gemm_mma<<<dim3(HMT, NT2), 256, GEMM_SMEM, s2>>>(HMT);
        itda_update  <<<HROWS, 256, 0, s2>>>(xs, HROWS);
    }
    itda_final<<<HROWS, 256, 0, s1>>>(xs, ys, y, wout, iout, xr, yr, ls, 0);
    itda_final<<<HROWS, 256, 0, s2>>>(xs, ys, y, wout, iout, xr, yr, ls, HROWS);

    // join back into the launch stream
    cudaEventRecord(ev1, s1);
    cudaEventRecord(ev2, s2);
    cudaStreamWaitEvent(0, ev1, 0);
    cudaStreamWaitEvent(0, ev2, 0);
}

// round 12
// speedup vs baseline: 1.1230x; 1.1230x over previous
#include <cuda_runtime.h>
#include <cuda_fp16.h>
#include <cstdint>

typedef unsigned long long ull;

#define Bsz 1024
#define Dd  1024
#define Ff  32768
#define L0  32
#define BN  128
#define NT  (Ff/BN)        // 256 column tiles
#define KC  64             // K dims per chunk
#define NCH (Dd/KC)        // 16 chunks
#define TILE_B 16384       // 128 rows x 64 fp16 = 16KB
#define NTSEL 10           // tiles rescored (2 atoms each)
#define NST 2              // GEMM pipeline stages (64KB -> 3 CTAs/SM)
#define HROWS 512          // rows per stream half
#define HMT   (HROWS/128)  // m-tiles per half
#define GEMM_SMEM (NST*2*TILE_B + 256)

// ---------------- persistent device scratch ----------------
__device__ float g_resid[Bsz*Dd];
__device__ __align__(16) ull g_xs_t[(size_t)Ff*Dd/4];   // 64MB fp16 tiled/swizzled dict
__device__ __align__(16) ull g_a_t[(size_t)Bsz*Dd/4];   // 2MB fp16 tiled residual
__device__ float g_cand_val[Bsz*NT];
__device__ int   g_cand_idx[Bsz*NT];
__device__ float g_cand_val2[Bsz*NT];
__device__ int   g_cand_idx2[Bsz*NT];
__device__ int   g_nsel[Bsz];
__device__ int   g_sel_idx[Bsz*34];
__device__ float g_sel_w[Bsz*34];

// ---------------- helpers ----------------
__device__ __forceinline__ uint32_t smem_u32(const void* p){
    uint32_t a; asm("{ .reg .u64 t; cvta.to.shared.u64 t, %1; cvt.u32.u64 %0, t; }"
                    : "=r"(a) : "l"(p)); return a;
}
__device__ __forceinline__ void cp16(uint32_t dst, const void* src){
    asm volatile("cp.async.cg.shared.global [%0], [%1], 16;" :: "r"(dst), "l"(src) : "memory");
}
__device__ __forceinline__ void cp_commit(){ asm volatile("cp.async.commit_group;" ::: "memory"); }
__device__ __forceinline__ void cp_wait1(){ asm volatile("cp.async.wait_group 1;" ::: "memory"); }
__device__ __forceinline__ void cp_wait0(){ asm volatile("cp.async.wait_group 0;" ::: "memory"); }
__device__ __forceinline__ void ldmx4(uint32_t* r, uint32_t addr){
    asm volatile("ldmatrix.sync.aligned.m8n8.x4.shared.b16 {%0,%1,%2,%3}, [%4];"
        : "=r"(r[0]), "=r"(r[1]), "=r"(r[2]), "=r"(r[3]) : "r"(addr));
}
// fp16 inputs, fp16 accumulators (2 regs)
__device__ __forceinline__ void mma_f16acc(uint32_t* d, const uint32_t* a, uint32_t b0, uint32_t b1){
    asm volatile("mma.sync.aligned.m16n8k16.row.col.f16.f16.f16.f16 "
        "{%0,%1}, {%2,%3,%4,%5}, {%6,%7}, {%0,%1};"
        : "+r"(d[0]), "+r"(d[1])
        : "r"(a[0]), "r"(a[1]), "r"(a[2]), "r"(a[3]), "r"(b0), "r"(b1));
}
__device__ __forceinline__ uint32_t swoff(int row, int colb){
    uint32_t o = (uint32_t)(row*128 + colb);
    return o ^ ((o >> 3) & 0x70);
}
__device__ __forceinline__ ull pack4h(float a, float b, float c, float d){
    const __half2 lo = __floats2half2_rn(a, b);
    const __half2 hi = __floats2half2_rn(c, d);
    const uint32_t ulo = *reinterpret_cast<const uint32_t*>(&lo);
    const uint32_t uhi = *reinterpret_cast<const uint32_t*>(&hi);
    return (ull)ulo | ((ull)uhi << 32);
}
__device__ __forceinline__ void store_resid_f16(int b, int tid, float4 v){
    const int m_tile = b >> 7, row = b & 127;
    const int kc = tid >> 4, cg = tid & 15;
    char* dst = (char*)g_a_t + (size_t)(m_tile*NCH + kc)*TILE_B;
    *(ull*)(dst + swoff(row, cg*8)) = pack4h(v.x, v.y, v.z, v.w);
}
__device__ __forceinline__ float block_sum(float v, float* s){
    const int lane = threadIdx.x & 31, w = threadIdx.x >> 5;
#pragma unroll
    for (int o = 16; o; o >>= 1) v += __shfl_xor_sync(0xffffffffu, v, o);
    __syncthreads();
    if (lane == 0) s[w] = v;
    __syncthreads();
    float r = 0.f;
#pragma unroll
    for (int i = 0; i < 8; i++) r += s[i];
    return r;
}
__device__ __forceinline__ bool better(float a, int ai, float b, int bi){
    return (a > b) || (a == b && ai < bi);
}
__device__ __forceinline__ void top2_push(float &v1, int &i1, float &v2, int &i2, float w, int j){
    if (better(w, j, v1, i1)){ v2 = v1; i2 = i1; v1 = w; i1 = j; }
    else if (better(w, j, v2, i2)){ v2 = w; i2 = j; }
}
// warp-parallel exact fp32 dot: atom (gmem) . residual (smem), 1024 dims
__device__ __forceinline__ float warp_dot(const float* __restrict__ atom,
                                          const float* __restrict__ s_resid, int lane){
    const float4* av = (const float4*)atom;
    const float4* rv = (const float4*)s_resid;
    float s = 0.f;
#pragma unroll
    for (int q = 0; q < 8; q++){
        const float4 a = av[lane + q*32];
        const float4 r = rv[lane + q*32];
        s += a.x*r.x + a.y*r.y + a.z*r.z + a.w*r.w;
    }
#pragma unroll
    for (int o = 16; o; o >>= 1) s += __shfl_xor_sync(0xffffffffu, s, o);
    return s;
}

// ---------------- K-1: dictionary -> tiled/swizzled fp16 ----------------
__global__ void conv_xs(const float* __restrict__ xs){
    const int tile = blockIdx.x;               // n_tile*NCH + kc
    const int n_tile = tile >> 4, kc = tile & 15;
    char* dst = (char*)g_xs_t + (size_t)tile*TILE_B;
    for (int g = threadIdx.x; g < 2048; g += 256){
        const int row = g >> 4, cg = g & 15;
        const float4 v = *(const float4*)(xs + (size_t)(n_tile*128 + row)*Dd + kc*KC + cg*4);
        *(ull*)(dst + swoff(row, cg*8)) = pack4h(v.x, v.y, v.z, v.w);
    }
}

// ---------------- K0: residual = x (half-batch) ----------------
__global__ void itda_init(const float* __restrict__ x, int row0){
    const int b = row0 + blockIdx.x;
    const float4 v = ((const float4*)(x + (size_t)b*Dd))[threadIdx.x];
    ((float4*)(g_resid + (size_t)b*Dd))[threadIdx.x] = v;
    store_resid_f16(b, threadIdx.x, v);
    if (threadIdx.x == 0) g_nsel[b] = 0;
}

// ---------------- K1: fp16 HMMA (f16 acc) GEMM, 2-stage, 3 CTAs/SM -------------
// CTA: 128(M) x 128(N) x K=1024. 8 warps: warp_m = wid&3 (32 rows), warp_n = wid>>2 (64 cols)
__global__ void __launch_bounds__(256, 3) itda_gemm_mma(int mt0){
    extern __shared__ __align__(16) char smem_raw[];
    uint32_t sb = (smem_u32(smem_raw) + 127u) & ~127u;
    const int tid = threadIdx.x, wid = tid >> 5, lane = tid & 31;
    const int mt = mt0 + blockIdx.x, nt = blockIdx.y;
    const int warp_m = wid & 3, warp_n = wid >> 2;

    const char* gA = (const char*)g_a_t  + (size_t)mt*NCH*TILE_B;
    const char* gB = (const char*)g_xs_t + (size_t)nt*NCH*TILE_B;

    uint32_t acc[2][8][2];                     // f16x2 accumulators
#pragma unroll
    for (int i = 0; i < 2; i++)
#pragma unroll
        for (int j = 0; j < 8; j++){ acc[i][j][0] = 0u; acc[i][j][1] = 0u; }

    const int lrow = ((lane >> 3) & 1)*8 + (lane & 7);
    const int lkb  = (lane >> 4)*16;
    const int rA0 = warp_m*32 + lrow;
    const int rB0 = warp_n*64 + lrow;

    auto issue = [&](int c, int s){
        const uint32_t dA = sb + s*32768 + tid*16;
        const uint32_t dB = dA + 16384;
        const char* srcA = gA + (size_t)c*TILE_B + tid*16;
        const char* srcB = gB + (size_t)c*TILE_B + tid*16;
#pragma unroll
        for (int i = 0; i < 4; i++){
            cp16(dA + i*4096, srcA + i*4096);
            cp16(dB + i*4096, srcB + i*4096);
        }
        cp_commit();
    };

    issue(0, 0);
    for (int c = 0; c < NCH; c++){
        const int s = c & 1;
        if (c + 1 < NCH){ issue(c + 1, s ^ 1); cp_wait1(); }
        else            { cp_wait0(); }
        __syncthreads();                       // stage s visible to all warps
        const uint32_t sA = sb + s*32768;
        const uint32_t sB = sA + 16384;
#pragma unroll
        for (int ks = 0; ks < 4; ks++){
            const int kb = ks*32 + lkb;
            uint32_t a[2][4];
            ldmx4(a[0], sA + swoff(rA0,      kb));
            ldmx4(a[1], sA + swoff(rA0 + 16, kb));
            uint32_t b[4][4];
#pragma unroll
            for (int nb = 0; nb < 4; nb++)
                ldmx4(b[nb], sB + swoff(rB0 + nb*16, kb));
#pragma unroll
            for (int mb = 0; mb < 2; mb++)
#pragma unroll
                for (int n8 = 0; n8 < 8; n8++){
                    const int nb = n8 >> 1, t = n8 & 1;
                    mma_f16acc(acc[mb][n8], a[mb], b[nb][t], b[nb][2+t]);
                }
        }
        __syncthreads();                       // stage s consumed before next-iter issue overwrites it
    }

    // epilogue: per-row TOP-2 (val, first-idx) over this 128-col tile
    float* sval1 = (float*)smem_raw;             // [128][2]
    int*   sidx1 = (int*)(smem_raw + 1024);
    float* sval2 = (float*)(smem_raw + 2048);
    int*   sidx2 = (int*)(smem_raw + 3072);
#pragma unroll
    for (int mb = 0; mb < 2; mb++)
#pragma unroll
        for (int h = 0; h < 2; h++){
            float v1 = -1e30f, v2 = -1e30f; int i1 = 0x7fffffff, i2 = 0x7fffffff;
#pragma unroll
            for (int n8 = 0; n8 < 8; n8++){
                const int c0 = n8*8 + (lane & 3)*2;
                const __half2 hh = *reinterpret_cast<const __half2*>(&acc[mb][n8][h]);
                const float2 f2 = __half22float2(hh);
                top2_push(v1, i1, v2, i2, f2.x, c0);
                top2_push(v1, i1, v2, i2, f2.y, c0+1);
            }
#pragma unroll
            for (int o = 1; o <= 2; o <<= 1){
                const float w1 = __shfl_xor_sync(0xffffffffu, v1, o);
                const int   j1 = __shfl_xor_sync(0xffffffffu, i1, o);
                const float w2 = __shfl_xor_sync(0xffffffffu, v2, o);
                const int   j2 = __shfl_xor_sync(0xffffffffu, i2, o);
                top2_push(v1, i1, v2, i2, w1, j1);
                top2_push(v1, i1, v2, i2, w2, j2);
            }
            if ((lane & 3) == 0){
                const int row = warp_m*32 + mb*16 + h*8 + (lane >> 2);
                sval1[row*2 + warp_n] = v1; sidx1[row*2 + warp_n] = warp_n*64 + i1;
                sval2[row*2 + warp_n] = v2; sidx2[row*2 + warp_n] = warp_n*64 + i2;
            }
        }
    __syncthreads();
    if (tid < 128){
        float v1 = sval1[tid*2]; int i1 = sidx1[tid*2];
        float v2 = sval2[tid*2]; int i2 = sidx2[tid*2];
        top2_push(v1, i1, v2, i2, sval1[tid*2+1], sidx1[tid*2+1]);
        top2_push(v1, i1, v2, i2, sval2[tid*2+1], sidx2[tid*2+1]);
        const int grow = mt*128 + tid;
        g_cand_val [grow*NT + nt] = v1;
        g_cand_idx [grow*NT + nt] = nt*BN + i1;
        g_cand_val2[grow*NT + nt] = v2;
        g_cand_idx2[grow*NT + nt] = nt*BN + i2;
    }
}

// ---------------- K2: warp-parallel rescore/grads + incremental residual -------
__global__ void itda_update(const float* __restrict__ xsm, int row0){
    const int b = row0 + blockIdx.x, tid = threadIdx.x;
    const int wid = tid >> 5, lane = tid & 31;
    __shared__ __align__(16) float s_resid[Dd];
    __shared__ float sred[8];
    __shared__ float s_tv[8];
    __shared__ int   s_ti[8];
    __shared__ int   s_wt[NTSEL];
    __shared__ int   s_win;
    __shared__ int   s_cand[2*NTSEL];
    __shared__ float s_dot[2*NTSEL];
    __shared__ int   s_list[34];
    __shared__ float s_w[34];
    __shared__ float s_grad[34];
    __shared__ int   s_n, s_newpos, s_bidx;
    __shared__ float s_bval;
    __shared__ int   s_nclip;
    __shared__ int   s_clip[34];
    __shared__ float s_cw[34];

    const float4 r4 = ((const float4*)(g_resid + (size_t)b*Dd))[tid];
    ((float4*)s_resid)[tid] = r4;
    if (tid == 0) s_nclip = 0;

    // --- select top-NTSEL tiles by screen tile max ---
    float cv = g_cand_val[b*NT + tid];
    for (int r = 0; r < NTSEL; r++){
        float v = cv; int t = tid;
#pragma unroll
        for (int o = 16; o; o >>= 1){
            const float ov = __shfl_xor_sync(0xffffffffu, v, o);
            const int   ot = __shfl_xor_sync(0xffffffffu, t, o);
            if (better(ov, ot, v, t)){ v = ov; t = ot; }
        }
        if (lane == 0){ s_tv[wid] = v; s_ti[wid] = t; }
        __syncthreads();
        if (tid == 0){
            float bv = s_tv[0]; int bt = s_ti[0];
#pragma unroll
            for (int i = 1; i < 8; i++)
                if (better(s_tv[i], s_ti[i], bv, bt)){ bv = s_tv[i]; bt = s_ti[i]; }
            s_wt[r] = bt; s_win = bt;
        }
        __syncthreads();
        if (tid == s_win) cv = -1e30f;
    }
    if (tid < NTSEL){
        const int w = s_wt[tid];
        s_cand[2*tid+0] = g_cand_idx [b*NT + w];
        s_cand[2*tid+1] = g_cand_idx2[b*NT + w];
    }
    __syncthreads();

    // --- exact fp32 rescore, warp-per-candidate ---
#pragma unroll
    for (int r = 0; r < (2*NTSEL + 7)/8; r++){
        const int k = wid + r*8;
        if (k < 2*NTSEL){
            const float d = warp_dot(xsm + (size_t)s_cand[k]*Dd, s_resid, lane);
            if (lane == 0) s_dot[k] = d;
        }
    }
    __syncthreads();
    if (wid == 0){
        float v = (lane < 2*NTSEL) ? s_dot[lane] : -1e30f;
        int   i = (lane < 2*NTSEL) ? s_cand[lane] : 0x7fffffff;
#pragma unroll
        for (int o = 16; o; o >>= 1){
            const float ov = __shfl_xor_sync(0xffffffffu, v, o);
            const int   oi = __shfl_xor_sync(0xffffffffu, i, o);
            if (better(ov, oi, v, i)){ v = ov; i = oi; }
        }
        if (lane == 0){ s_bidx = i; s_bval = v; }
    }
    __syncthreads();
    const int bidx = s_bidx;

    // --- active list: S = {w>0} U {argmax} ---
    const int n0 = g_nsel[b];
    if (tid < n0){ s_list[tid] = g_sel_idx[b*34 + tid]; s_w[tid] = g_sel_w[b*34 + tid]; }
    __syncthreads();
    if (tid == 0){
        int pos = -1, n = n0;
        for (int j = 0; j < n; j++) if (s_list[j] == bidx){ pos = j; break; }
        if (pos < 0){ pos = n; s_list[n] = bidx; s_w[n] = 0.f; n++; }
        s_n = n; s_newpos = pos;
    }
    __syncthreads();
    const int n = s_n, newpos = s_newpos;

    // --- grads, warp-per-atom ---
    for (int r = 0; r < (n + 7) >> 3; r++){
        const int j = wid + r*8;
        if (j < n){
            if (j == newpos){
                if (lane == 0) s_grad[j] = s_bval;
            } else if (s_w[j] > 0.f){
                const float g = warp_dot(xsm + (size_t)s_list[j]*Dd, s_resid, lane);
                if (lane == 0) s_grad[j] = g;
            } else if (lane == 0) s_grad[j] = 0.f;
        }
    }
    __syncthreads();

    // --- c = grad @ xs (per-thread 4-dim slice) ---
    float4 c4 = make_float4(0.f,0.f,0.f,0.f);
    for (int j = 0; j < n; j++){
        const float g = s_grad[j];
        if (g != 0.f){
            const float4 v = ((const float4*)(xsm + (size_t)s_list[j]*Dd))[tid];
            c4.x += g*v.x; c4.y += g*v.y; c4.z += g*v.z; c4.w += g*v.w;
        }
    }
    const float csq  = block_sum(c4.x*c4.x + c4.y*c4.y + c4.z*c4.z + c4.w*c4.w, sred);
    const float cr   = block_sum(c4.x*r4.x + c4.y*r4.y + c4.z*r4.z + c4.w*r4.w, sred);
    const float step = cr / fmaxf(csq, 1e-3f);

    // --- weight update + clip detection ---
    if (tid < n){
        const float g  = s_grad[tid];
        const float wn = s_w[tid] + step * g;
        s_w[tid] = fmaxf(wn, 0.f);
        if (g != 0.f && wn < 0.f){
            const int p = atomicAdd(&s_nclip, 1);
            s_clip[p] = tid; s_cw[p] = wn;
        }
    }
    __syncthreads();

    // --- incremental residual: r' = r - step*c + sum_clipped (w+s*g)*v ---
    float4 xv;
    xv.x = r4.x - step*c4.x; xv.y = r4.y - step*c4.y;
    xv.z = r4.z - step*c4.z; xv.w = r4.w - step*c4.w;
    const int nclip = s_nclip;
    for (int q = 0; q < nclip; q++){
        const float wneg = s_cw[q];
        const float4 v = ((const float4*)(xsm + (size_t)s_list[s_clip[q]]*Dd))[tid];
        xv.x += wneg*v.x; xv.y += wneg*v.y; xv.z += wneg*v.z; xv.w += wneg*v.w;
    }
    ((float4*)(g_resid + (size_t)b*Dd))[tid] = xv;
    store_resid_f16(b, tid, xv);

    if (tid == 0) g_nsel[b] = n;
    if (tid < n){ g_sel_idx[b*34 + tid] = s_list[tid]; g_sel_w[b*34 + tid] = s_w[tid]; }
}

// ---------------- K3: top_k ordering, padding, decode, losses (half-batch) -----
__global__ void itda_final(const float* __restrict__ xsm, const float* __restrict__ ysm,
                           const float* __restrict__ y,
                           float* __restrict__ wout, float* __restrict__ iout,
                           float* __restrict__ xr, float* __restrict__ yr,
                           float* __restrict__ ls, int row0){
    const int b = row0 + blockIdx.x, tid = threadIdx.x;
    __shared__ int   pi[33];
    __shared__ float pw[33];
    __shared__ int   oidx[32];
    __shared__ float ow[32];
    __shared__ int   s_np;
    __shared__ float sred[8];

    if (tid == 0){
        const int nl = g_nsel[b];
        int np = 0;
        for (int j = 0; j < nl; j++){
            const float w = g_sel_w[b*34 + j];
            if (w > 0.f){ pi[np] = g_sel_idx[b*34 + j]; pw[np] = w; np++; }
        }
        for (int a = 0; a < np; a++){
            int bst = a;
            for (int c = a+1; c < np; c++)
                if (pw[c] > pw[bst] || (pw[c] == pw[bst] && pi[c] < pi[bst])) bst = c;
            const float tw = pw[a]; pw[a] = pw[bst]; pw[bst] = tw;
            const int   ti = pi[a]; pi[a] = pi[bst]; pi[bst] = ti;
        }
        int f = 0;
        for (int k = 0; k < L0; k++){
            if (k < np){ ow[k] = pw[k]; oidx[k] = pi[k]; }
            else {
                for (;;){
                    bool used = false;
                    for (int q = 0; q < np; q++) if (pi[q] == f){ used = true; break; }
                    if (!used) break;
                    f++;
                }
                oidx[k] = f; ow[k] = 0.f; f++;
            }
        }
        s_np = np;
    }
    __syncthreads();

    if (tid < L0){
        wout[b*L0 + tid] = ow[tid];
        iout[b*L0 + tid] = (float)oidx[tid];
    }
    const int np = s_np;

    float4 ax = make_float4(0.f,0.f,0.f,0.f);
    float4 ay = make_float4(0.f,0.f,0.f,0.f);
    for (int k = 0; k < np; k++){
        const float w = ow[k];
        const size_t off = (size_t)oidx[k]*Dd;
        const float4 vx = ((const float4*)(xsm + off))[tid];
        const float4 vy = ((const float4*)(ysm + off))[tid];
        ax.x += w*vx.x; ax.y += w*vx.y; ax.z += w*vx.z; ax.w += w*vx.w;
        ay.x += w*vy.x; ay.y += w*vy.y; ay.z += w*vy.z; ay.w += w*vy.w;
    }
    ((float4*)(xr + (size_t)b*Dd))[tid] = ax;
    ((float4*)(yr + (size_t)b*Dd))[tid] = ay;

    const float4 yv = ((const float4*)(y + (size_t)b*Dd))[tid];
    const float d0 = ay.x - yv.x, d1 = ay.y - yv.y, d2 = ay.z - yv.z, d3 = ay.w - yv.w;
    const float L = block_sum(d0*d0 + d1*d1 + d2*d2 + d3*d3, sred);
    if (tid == 0) ls[b] = L;
}

// ---------------- entry: two forked capture streams, row-disjoint halves -------
extern "C" void kernel_launch(void* const* d_in, const int* in_sizes, int n_in,
                              void* d_out, int out_size){
    const float* x  = (const float*)d_in[0];
    const float* y  = (const float*)d_in[1];
    const float* xs = (const float*)d_in[2];
    const float* ys = (const float*)d_in[3];

    float* out  = (float*)d_out;
    float* wout = out;                    // [1024, 32]
    float* iout = out + Bsz*L0;           // [1024, 32] indices as float
    float* xr   = iout + Bsz*L0;          // [1024, 1024]
    float* yr   = xr + (size_t)Bsz*Dd;    // [1024, 1024]
    float* ls   = yr + (size_t)Bsz*Dd;    // [1024]

    static cudaStream_t s1 = nullptr, s2 = nullptr;
    static cudaEvent_t ev0 = nullptr, evc = nullptr, ev1 = nullptr, ev2 = nullptr;
    if (!s1){
        cudaStreamCreateWithFlags(&s1, cudaStreamNonBlocking);
        cudaStreamCreateWithFlags(&s2, cudaStreamNonBlocking);
        cudaEventCreateWithFlags(&ev0, cudaEventDisableTiming);
        cudaEventCreateWithFlags(&evc, cudaEventDisableTiming);
        cudaEventCreateWithFlags(&ev1, cudaEventDisableTiming);
        cudaEventCreateWithFlags(&ev2, cudaEventDisableTiming);
        cudaFuncSetAttribute(itda_gemm_mma, cudaFuncAttributeMaxDynamicSharedMemorySize, GEMM_SMEM);
    }

    // fork both worker streams off the launch stream
    cudaEventRecord(ev0, 0);
    cudaStreamWaitEvent(s1, ev0, 0);
    cudaStreamWaitEvent(s2, ev0, 0);

    // dict conversion on s1; s2 waits for it before its first GEMM
    conv_xs<<<NT*NCH, 256, 0, s1>>>(xs);
    cudaEventRecord(evc, s1);
    cudaStreamWaitEvent(s2, evc, 0);

    itda_init<<<HROWS, 256, 0, s1>>>(x, 0);
    itda_init<<<HROWS, 256, 0, s2>>>(x, HROWS);

    for (int it = 0; it < L0; it++){
        itda_gemm_mma<<<dim3(HMT, NT), 256, GEMM_SMEM, s1>>>(0);
        itda_update  <<<HROWS, 256, 0, s1>>>(xs, 0);
        itda_gemm_mma<<<dim3(HMT, NT), 256, GEMM_SMEM, s2>>>(HMT);
        itda_update  <<<HROWS, 256, 0, s2>>>(xs, HROWS);
    }
    itda_final<<<HROWS, 256, 0, s1>>>(xs, ys, y, wout, iout, xr, yr, ls, 0);
    itda_final<<<HROWS, 256, 0, s2>>>(xs, ys, y, wout, iout, xr, yr, ls, HROWS);

    // join back into the launch stream
    cudaEventRecord(ev1, s1);
    cudaEventRecord(ev2, s2);
    cudaStreamWaitEvent(0, ev1, 0);
    cudaStreamWaitEvent(0, ev2, 0);
}